// round 11
// baseline (speedup 1.0000x reference)
#include <cuda_runtime.h>
#include <math.h>
#include <stdint.h>

#define N_NODES   50000
#define N_EDGES   800000
#define IN_DIM    128
#define EDGE_DIM  16
#define HID       128
#define N_LAYERS  3
#define N_GRAPHS  256
#define BN_EPS    1e-5f

// fragment-major weight layout (R6-proven)
#define FRAG_PITCH 260
#define SLAB_WORDS (64 * FRAG_PITCH)   // 16640 (K=128 slab)
#define W1E_WORDS  (8 * FRAG_PITCH)    // 2080  (K=16 slab)

// ---------------- scratch ----------------
__device__ float    g_h[N_NODES * HID];
__device__ float    g_agg[N_NODES * HID];
__device__ float    g_p[N_NODES * HID];
__device__ float    g_gi[N_NODES * 3 * HID];
__device__ float    g_gh[N_NODES * 3 * HID];
__device__ unsigned g_wpack[25 * SLAB_WORDS + 3 * W1E_WORDS];
__device__ float    g_rsum[N_GRAPHS * HID];
__device__ unsigned g_rmax[N_GRAPHS * HID];
__device__ int      g_rcnt[N_GRAPHS];
// edge sort-by-dst
__device__ int      g_cnt[N_NODES];
__device__ int      g_cur[N_NODES];
__device__ int      g_srcS[N_EDGES];
__device__ int      g_dstS[N_EDGES];
__device__ int      g_permE[N_EDGES];

// ---------------- helpers ----------------
__device__ __forceinline__ unsigned fenc(float f) {
    unsigned u = __float_as_uint(f);
    return (u & 0x80000000u) ? ~u : (u | 0x80000000u);
}
__device__ __forceinline__ float fdec(unsigned k) {
    return __uint_as_float((k & 0x80000000u) ? (k & 0x7fffffffu) : ~k);
}
__device__ __forceinline__ unsigned f2tf(float f) {
    unsigned u;
    asm("cvt.rna.tf32.f32 %0, %1;" : "=r"(u) : "f"(f));
    return u;
}
__device__ __forceinline__ void mma_tf32(float* c, const unsigned* a,
                                         unsigned b0, unsigned b1) {
    asm volatile(
        "mma.sync.aligned.m16n8k8.row.col.f32.tf32.tf32.f32 "
        "{%0,%1,%2,%3}, {%4,%5,%6,%7}, {%8,%9}, {%0,%1,%2,%3};"
        : "+f"(c[0]), "+f"(c[1]), "+f"(c[2]), "+f"(c[3])
        : "r"(a[0]), "r"(a[1]), "r"(a[2]), "r"(a[3]), "r"(b0), "r"(b1));
}
__device__ __forceinline__ void cp16(uint32_t s, const void* g) {
    asm volatile("cp.async.cg.shared.global [%0], [%1], 16;" :: "r"(s), "l"(g));
}
// fragment word offset within a slab
__device__ __forceinline__ int frag_off(int ks, int tg, int wn, int gid,
                                        int nt, int pair) {
    return (ks * 4 + tg) * FRAG_PITCH + ((wn * 8 + gid) * 8 + nt) * 2 + pair;
}

// ---------------- weight pre-pack ----------------
__global__ void pack_all(const float* __restrict__ linW,
                         const float* __restrict__ w1,
                         const float* __restrict__ wih,
                         const float* __restrict__ whh,
                         const float* __restrict__ w2) {
    int idx = blockIdx.x * blockDim.x + threadIdx.x;
    const int NMAIN = 25 * 16384;
    if (idx < NMAIN) {
        int slab = idx >> 14, r = idx & 16383;
        int pair = r & 1, nt = (r >> 1) & 7, gid = (r >> 4) & 7;
        int wn = (r >> 7) & 1, tg = (r >> 8) & 3, ks = r >> 10;
        int row = ks * 8 + tg + pair * 4;
        int col = wn * 64 + nt * 8 + gid;
        float v;
        if (slab == 0)      v = linW[row * 128 + col];
        else if (slab < 4)  { int l = slab - 1;
            v = w1[(size_t)l * 144 * 128 + row * 128 + col]; }
        else if (slab < 13) { int t = slab - 4, l = t / 3, j = t % 3;
            v = wih[(size_t)l * 384 * 128 + (size_t)(j * 128 + col) * 128 + row]; }
        else if (slab < 22) { int t = slab - 13, l = t / 3, j = t % 3;
            v = whh[(size_t)l * 384 * 128 + (size_t)(j * 128 + col) * 128 + row]; }
        else                { int l = slab - 22;
            v = w2[(size_t)l * 128 * 128 + row * 128 + col]; }
        g_wpack[slab * SLAB_WORDS + frag_off(ks, tg, wn, gid, nt, pair)] = f2tf(v);
    } else {
        int r2 = idx - NMAIN;
        if (r2 >= 3 * 2048) return;
        int l = r2 >> 11, r = r2 & 2047;
        int pair = r & 1, nt = (r >> 1) & 7, gid = (r >> 4) & 7;
        int wn = (r >> 7) & 1, tg = (r >> 8) & 3, ks = r >> 10;
        int row = ks * 8 + tg + pair * 4;
        int col = wn * 64 + nt * 8 + gid;
        float v = w1[(size_t)l * 144 * 128 + (size_t)(128 + row) * 128 + col];
        g_wpack[25 * SLAB_WORDS + l * W1E_WORDS
                + frag_off(ks, tg, wn, gid, nt, pair)] = f2tf(v);
    }
}

// ---------------- edge counting sort ----------------
__global__ void hist_zero() {
    int i = blockIdx.x * blockDim.x + threadIdx.x;
    if (i < N_NODES) g_cnt[i] = 0;
}
__global__ void hist_build(const int* __restrict__ dst) {
    int e = blockIdx.x * blockDim.x + threadIdx.x;
    if (e < N_EDGES) atomicAdd(&g_cnt[dst[e]], 1);
}
__global__ void __launch_bounds__(1024) scan_offsets() {
    __shared__ int part[1024];
    int t = threadIdx.x;
    const int CH = 49;  // 1024*49 = 50176 >= 50000
    int beg = t * CH, end = min(beg + CH, N_NODES);
    int s = 0;
    for (int i = beg; i < end; i++) s += g_cnt[i];
    part[t] = s;
    __syncthreads();
    for (int off = 1; off < 1024; off <<= 1) {
        int v = (t >= off) ? part[t - off] : 0;
        __syncthreads();
        part[t] += v;
        __syncthreads();
    }
    int run = (t == 0) ? 0 : part[t - 1];
    for (int i = beg; i < end; i++) {
        int c = g_cnt[i];
        g_cnt[i] = run;
        g_cur[i] = run;
        run += c;
    }
}
__global__ void scatter_sort(const int* __restrict__ src,
                             const int* __restrict__ dst) {
    int e = blockIdx.x * blockDim.x + threadIdx.x;
    if (e >= N_EDGES) return;
    int d = dst[e];
    int pos = atomicAdd(&g_cur[d], 1);
    g_srcS[pos] = src[e];
    g_dstS[pos] = d;
    g_permE[pos] = e;
}

// ---------------- zero ----------------
__global__ void zero_agg_kernel() {
    int i = blockIdx.x * blockDim.x + threadIdx.x;
    if (i < (N_NODES * HID) / 4)
        ((float4*)g_agg)[i] = make_float4(0.f, 0.f, 0.f, 0.f);
}
__global__ void zero_readout_kernel() {
    int i = blockIdx.x * blockDim.x + threadIdx.x;
    if (i < N_GRAPHS * HID) { g_rsum[i] = 0.f; g_rmax[i] = 0u; }
    if (i < N_GRAPHS) g_rcnt[i] = 0;
}

// ---------------- persistent dense tf32 GEMM, 512 threads ----------------
#define PD_WORDS (SLAB_WORDS + 2 * 128 * 132)
#define PD_SMEM  (PD_WORDS * 4)
__global__ void __launch_bounds__(512)
pdense(const float* __restrict__ Aa, const unsigned* __restrict__ pka,
       const float* __restrict__ biasa, float* __restrict__ Ca,
       const float* __restrict__ Ab, const unsigned* __restrict__ pkb,
       const float* __restrict__ biasb, float* __restrict__ Cb,
       int M, int nC, int nslabA, int relu) {
    extern __shared__ unsigned psm[];
    unsigned* sB = psm;
    float*    sA = (float*)(psm + SLAB_WORDS);
    int slab = blockIdx.y;
    const float *A, *bias; float* C; const unsigned* wp; int n0;
    if (slab < nslabA) { A = Aa; bias = biasa; C = Ca;
        wp = pka + (size_t)slab * SLAB_WORDS; n0 = slab * 128; }
    else { A = Ab; bias = biasb; C = Cb;
        wp = pkb + (size_t)(slab - nslabA) * SLAB_WORDS; n0 = (slab - nslabA) * 128; }

    int tid = threadIdx.x, lane = tid & 31, wid = tid >> 5;
    int wm = wid & 7, wn = wid >> 3, gid = lane >> 2, tg = lane & 3;
    int r4 = tid >> 2, q = tid & 3;
    uint32_t sa_u32 = (uint32_t)__cvta_generic_to_shared(sA);
    uint32_t sb_u32 = (uint32_t)__cvta_generic_to_shared(sB);

    const int tiles = (M + 127) >> 7;
    for (int i = tid; i < SLAB_WORDS / 4; i += 512)
        cp16(sb_u32 + i * 16, wp + i * 4);
    {
        int gm = blockIdx.x * 128 + r4; if (gm >= M) gm = M - 1;
        const float* ar = A + (size_t)gm * 128 + q * 32;
        uint32_t sa = sa_u32 + (r4 * 132 + q * 32) * 4;
#pragma unroll
        for (int k = 0; k < 8; k++) cp16(sa + k * 16, ar + k * 4);
    }
    asm volatile("cp.async.commit_group;");

    int buf = 0;
    for (int t = blockIdx.x; t < tiles; t += gridDim.x) {
        int tn = t + gridDim.x;
        if (tn < tiles) {
            int gm = tn * 128 + r4; if (gm >= M) gm = M - 1;
            const float* ar = A + (size_t)gm * 128 + q * 32;
            uint32_t sa = sa_u32 + ((buf ^ 1) * 128 * 132 + r4 * 132 + q * 32) * 4;
#pragma unroll
            for (int k = 0; k < 8; k++) cp16(sa + k * 16, ar + k * 4);
        }
        asm volatile("cp.async.commit_group;");
        asm volatile("cp.async.wait_group 1;");
        __syncthreads();

        const unsigned* sAu = (const unsigned*)(sA + buf * 128 * 132);
        float acc[8][4];
#pragma unroll
        for (int nt = 0; nt < 8; nt++)
#pragma unroll
            for (int i = 0; i < 4; i++) acc[nt][i] = 0.f;

        int R = wm * 16 + gid;
        int bbase = (wn * 8 + gid) * 16;
#pragma unroll 4
        for (int ks = 0; ks < 16; ks++) {
            unsigned a[4];
            int col = ks * 8 + tg;
            a[0] = sAu[R * 132 + col];
            a[1] = sAu[(R + 8) * 132 + col];
            a[2] = sAu[R * 132 + col + 4];
            a[3] = sAu[(R + 8) * 132 + col + 4];
            const uint4* bp = (const uint4*)(sB + (ks * 4 + tg) * FRAG_PITCH + bbase);
#pragma unroll
            for (int j = 0; j < 4; j++) {
                uint4 b = bp[j];
                mma_tf32(acc[2 * j],     a, b.x, b.y);
                mma_tf32(acc[2 * j + 1], a, b.z, b.w);
            }
        }

        int m0 = t * 128;
#pragma unroll
        for (int nt = 0; nt < 8; nt++)
#pragma unroll
            for (int p = 0; p < 2; p++) {
                int gm = m0 + R + p * 8;
                if (gm < M) {
                    int col = wn * 64 + nt * 8 + 2 * tg;
                    float2 v;
                    v.x = acc[nt][p * 2]     + __ldg(bias + n0 + col);
                    v.y = acc[nt][p * 2 + 1] + __ldg(bias + n0 + col + 1);
                    if (relu) { v.x = fmaxf(v.x, 0.f); v.y = fmaxf(v.y, 0.f); }
                    *(float2*)(C + (size_t)gm * nC + n0 + col) = v;
                }
            }
        __syncthreads();
        buf ^= 1;
    }
}

// ---------------- edge kernel, 512 threads, sorted-dst ----------------
#define EW_W2   0
#define EW_W1E  SLAB_WORDS                    // 16640
#define EW_A    (EW_W1E + W1E_WORDS)          // 18720 : 2 bufs of 128x132
#define EW_E    (EW_A + 2 * 128 * 132)        // 52512 : 2 bufs of 128x16
#define EDGE_WORDS (EW_E + 2 * 128 * 16)      // 56608
#define EDGE_SMEM (EDGE_WORDS * 4)            // 226432 B

__global__ void __launch_bounds__(512)
edge_kernel(const float* __restrict__ eattr,
            const unsigned* __restrict__ W1epk,
            const unsigned* __restrict__ W2pk,
            const float* __restrict__ b2) {
    extern __shared__ unsigned smu[];
    unsigned* sW2  = smu + EW_W2;
    unsigned* sW1e = smu + EW_W1E;
    float*    smf  = (float*)smu;
    __shared__ float sB2[128];
    __shared__ int   sDst[128];
    uint32_t smem_u32 = (uint32_t)__cvta_generic_to_shared(smu);

    int tid = threadIdx.x, lane = tid & 31, wid = tid >> 5;
    int wm = wid & 7, wn = wid >> 3, gid = lane >> 2, tg = lane & 3;
    int r4 = tid >> 2, q = tid & 3;

    // prologue: packed weights + first P/E gather (sorted), one cp.async group
    for (int i = tid; i < SLAB_WORDS / 4; i += 512)
        cp16(smem_u32 + i * 16, W2pk + i * 4);
    for (int i = tid; i < W1E_WORDS / 4; i += 512)
        cp16(smem_u32 + EW_W1E * 4 + i * 16, W1epk + i * 4);
    {
        int e0 = blockIdx.x * 128;
        int s = __ldg(g_srcS + e0 + r4);
        const float* pr = g_p + (size_t)s * HID + q * 32;
        uint32_t sa = smem_u32 + (EW_A + r4 * 132 + q * 32) * 4;
#pragma unroll
        for (int k = 0; k < 8; k++) cp16(sa + k * 16, pr + k * 4);
        int pe = __ldg(g_permE + e0 + r4);
        cp16(smem_u32 + (EW_E + r4 * 16 + q * 4) * 4,
             eattr + (size_t)pe * EDGE_DIM + q * 4);
    }
    asm volatile("cp.async.commit_group;");
    if (tid < 128) sB2[tid] = b2[tid];

    const int ntiles = N_EDGES / 128;  // 6250
    int buf = 0;
    for (int t = blockIdx.x; t < ntiles; t += gridDim.x) {
        int tn = t + gridDim.x;
        if (tn < ntiles) {  // prefetch next tile's P + E into buf^1
            int e0n = tn * 128;
            int s = __ldg(g_srcS + e0n + r4);
            const float* pr = g_p + (size_t)s * HID + q * 32;
            uint32_t sa = smem_u32 + (EW_A + (buf ^ 1) * (128 * 132) + r4 * 132 + q * 32) * 4;
#pragma unroll
            for (int k = 0; k < 8; k++) cp16(sa + k * 16, pr + k * 4);
            int pe = __ldg(g_permE + e0n + r4);
            cp16(smem_u32 + (EW_E + (buf ^ 1) * (128 * 16) + r4 * 16 + q * 4) * 4,
                 eattr + (size_t)pe * EDGE_DIM + q * 4);
        }
        asm volatile("cp.async.commit_group;");
        asm volatile("cp.async.wait_group 1;");
        __syncthreads();

        float*    sAf = smf + EW_A + buf * (128 * 132);
        unsigned* sAu = (unsigned*)sAf;
        unsigned* sEu = smu + EW_E + buf * (128 * 16);
        int e0 = t * 128;
        int R = wm * 16 + gid;
        int bbase = (wn * 8 + gid) * 16;

        if (tid < 128) sDst[tid] = __ldg(g_dstS + e0 + tid);

        // stage 1: acc = P[src] (fp32) + eattr @ W1e (K=16)
        float acc[8][4];
#pragma unroll
        for (int nt = 0; nt < 8; nt++) {
            int Cc = wn * 64 + nt * 8 + 2 * tg;
            float2 v0 = *(float2*)(sAf + R * 132 + Cc);
            float2 v1 = *(float2*)(sAf + (R + 8) * 132 + Cc);
            acc[nt][0] = v0.x; acc[nt][1] = v0.y;
            acc[nt][2] = v1.x; acc[nt][3] = v1.y;
        }
#pragma unroll
        for (int ks = 0; ks < 2; ks++) {
            unsigned a[4];
            int col = ks * 8 + tg;
            a[0] = sEu[R * 16 + col];
            a[1] = sEu[(R + 8) * 16 + col];
            a[2] = sEu[R * 16 + col + 4];
            a[3] = sEu[(R + 8) * 16 + col + 4];
            const uint4* bp = (const uint4*)(sW1e + (ks * 4 + tg) * FRAG_PITCH + bbase);
#pragma unroll
            for (int j = 0; j < 4; j++) {
                uint4 b = bp[j];
                mma_tf32(acc[2 * j],     a, b.x, b.y);
                mma_tf32(acc[2 * j + 1], a, b.z, b.w);
            }
        }
        // relu -> hidden (tf32), in place over the P buffer
#pragma unroll
        for (int nt = 0; nt < 8; nt++) {
            int col = wn * 64 + nt * 8 + 2 * tg;
            uint2 w0, w1;
            w0.x = f2tf(fmaxf(acc[nt][0], 0.f));
            w0.y = f2tf(fmaxf(acc[nt][1], 0.f));
            w1.x = f2tf(fmaxf(acc[nt][2], 0.f));
            w1.y = f2tf(fmaxf(acc[nt][3], 0.f));
            *(uint2*)(sAu + R * 132 + col) = w0;
            *(uint2*)(sAu + (R + 8) * 132 + col) = w1;
        }
        __syncthreads();

        // stage 2: m = hidden @ W2 (K=128)
#pragma unroll
        for (int nt = 0; nt < 8; nt++)
#pragma unroll
            for (int i = 0; i < 4; i++) acc[nt][i] = 0.f;
#pragma unroll 4
        for (int ks = 0; ks < 16; ks++) {
            unsigned a[4];
            int col = ks * 8 + tg;
            a[0] = sAu[R * 132 + col];
            a[1] = sAu[(R + 8) * 132 + col];
            a[2] = sAu[R * 132 + col + 4];
            a[3] = sAu[(R + 8) * 132 + col + 4];
            const uint4* bp = (const uint4*)(sW2 + (ks * 4 + tg) * FRAG_PITCH + bbase);
#pragma unroll
            for (int j = 0; j < 4; j++) {
                uint4 b = bp[j];
                mma_tf32(acc[2 * j],     a, b.x, b.y);
                mma_tf32(acc[2 * j + 1], a, b.z, b.w);
            }
        }
        __syncthreads();   // everyone done reading sAu

        // stage outputs (raw, bias added in reduce) back into sAf
#pragma unroll
        for (int nt = 0; nt < 8; nt++) {
            int col = wn * 64 + nt * 8 + 2 * tg;
            *(float2*)(sAf + R * 132 + col) = make_float2(acc[nt][0], acc[nt][1]);
            *(float2*)(sAf + (R + 8) * 132 + col) = make_float2(acc[nt][2], acc[nt][3]);
        }
        __syncthreads();

        // segmented reduction over sorted dst: thread = (col, 32-row group)
        {
            int col = tid & 127, rg = tid >> 7;
            float bb = sB2[col];
            int rbase = rg * 32;
            int curd = sDst[rbase];
            float s = 0.f;
            for (int r = 0; r < 32; r++) {
                int d = sDst[rbase + r];
                float v = sAf[(rbase + r) * 132 + col] + bb;
                if (d != curd) {
                    atomicAdd(&g_agg[(size_t)curd * HID + col], s);
                    s = 0.f; curd = d;
                }
                s += v;
            }
            atomicAdd(&g_agg[(size_t)curd * HID + col], s);
        }
        __syncthreads();   // reduce done before next prefetch reuses buffers
        buf ^= 1;
    }
}

// ---------------- GRU gates + BN + residual (+ zero agg) ----------------
__global__ void gru_epi_kernel(const float* __restrict__ gamma,
                               const float* __restrict__ beta,
                               const float* __restrict__ mean,
                               const float* __restrict__ var) {
    int idx = blockIdx.x * blockDim.x + threadIdx.x;
    if (idx >= N_NODES * HID) return;
    int n = idx >> 7, j = idx & 127;
    const float* gi = g_gi + (size_t)n * 384;
    const float* gh = g_gh + (size_t)n * 384;
    float ir = gi[j], iz = gi[128 + j], inn = gi[256 + j];
    float hr = gh[j], hz = gh[128 + j], hn  = gh[256 + j];
    float h = g_h[idx];
    float r = 1.f / (1.f + __expf(-(ir + hr)));
    float z = 1.f / (1.f + __expf(-(iz + hz)));
    float nn = tanhf(inn + r * hn);
    float hnew = (1.f - z) * nn + z * h;
    float bn = (hnew - mean[j]) * rsqrtf(var[j] + BN_EPS) * gamma[j] + beta[j];
    g_h[idx] = h + bn;
    g_agg[idx] = 0.f;
}

// ---------------- readout ----------------
__global__ void readout_acc_kernel(const int* __restrict__ batch) {
    __shared__ int sb[128];
    int j = threadIdx.x;
    int nBeg = blockIdx.x * 128;
    int cnt = min(128, N_NODES - nBeg);
    sb[j] = (j < cnt) ? __ldg(batch + nBeg + j) : -1;
    __syncthreads();
    int curb = sb[0];
    float s = 0.f; unsigned mx = 0u; int c = 0;
    for (int i = 0; i < cnt; i++) {
        int b = sb[i];
        float v = g_h[(size_t)(nBeg + i) * HID + j];
        if (b != curb) {
            atomicAdd(&g_rsum[curb * HID + j], s);
            atomicMax(&g_rmax[curb * HID + j], mx);
            if (j == 0) atomicAdd(&g_rcnt[curb], c);
            s = 0.f; mx = 0u; c = 0; curb = b;
        }
        s += v; mx = max(mx, fenc(v)); c++;
    }
    if (c > 0) {
        atomicAdd(&g_rsum[curb * HID + j], s);
        atomicMax(&g_rmax[curb * HID + j], mx);
        if (j == 0) atomicAdd(&g_rcnt[curb], c);
    }
}
__global__ void readout_final_kernel(const float* __restrict__ roW,
                                     const float* __restrict__ roB,
                                     float* __restrict__ out) {
    __shared__ float s[2 * HID];
    int g = blockIdx.x, j = threadIdx.x;
    int cnt = g_rcnt[g];
    float mv = g_rsum[g * HID + j] / fmaxf((float)cnt, 1.f);
    float xv = (cnt > 0) ? fdec(g_rmax[g * HID + j]) : 0.f;
    s[j] = mv;
    s[HID + j] = xv;
    __syncthreads();
    float acc = roB[j];
    for (int k = 0; k < 2 * HID; k++) acc += s[k] * roW[k * HID + j];
    out[g * HID + j] = fmaxf(acc, 0.f);
}

// ---------------- launch ----------------
extern "C" void kernel_launch(void* const* d_in, const int* in_sizes, int n_in,
                              void* d_out, int out_size) {
    int base = (in_sizes[4] <= 2) ? 5 : 4;
    const float* x     = (const float*)d_in[0];
    const int*   eidx  = (const int*)d_in[1];
    const float* eattr = (const float*)d_in[2];
    const int*   batch = (const int*)d_in[3];
    const float* linW  = (const float*)d_in[base + 0];
    const float* linB  = (const float*)d_in[base + 1];
    const float* w1    = (const float*)d_in[base + 2];
    const float* b1    = (const float*)d_in[base + 3];
    const float* w2    = (const float*)d_in[base + 4];
    const float* b2    = (const float*)d_in[base + 5];
    const float* bng   = (const float*)d_in[base + 6];
    const float* bnb   = (const float*)d_in[base + 7];
    const float* bnm   = (const float*)d_in[base + 8];
    const float* bnv   = (const float*)d_in[base + 9];
    const float* wih   = (const float*)d_in[base + 10];
    const float* whh   = (const float*)d_in[base + 11];
    const float* bih   = (const float*)d_in[base + 12];
    const float* bhh   = (const float*)d_in[base + 13];
    const float* roW   = (const float*)d_in[base + 14];
    const float* roB   = (const float*)d_in[base + 15];
    float* out = (float*)d_out;

    cudaFuncSetAttribute(pdense,      cudaFuncAttributeMaxDynamicSharedMemorySize, PD_SMEM);
    cudaFuncSetAttribute(edge_kernel, cudaFuncAttributeMaxDynamicSharedMemorySize, EDGE_SMEM);

    float *hp, *aggp, *pp, *gip, *ghp;
    unsigned* wpk;
    cudaGetSymbolAddress((void**)&hp,   g_h);
    cudaGetSymbolAddress((void**)&aggp, g_agg);
    cudaGetSymbolAddress((void**)&pp,   g_p);
    cudaGetSymbolAddress((void**)&gip,  g_gi);
    cudaGetSymbolAddress((void**)&ghp,  g_gh);
    cudaGetSymbolAddress((void**)&wpk,  g_wpack);

    // weight pre-pack + edge counting-sort (independent of compute prologue)
    pack_all<<<(25 * 16384 + 3 * 2048 + 511) / 512, 512>>>(linW, w1, wih, whh, w2);
    hist_zero<<<(N_NODES + 255) / 256, 256>>>();
    hist_build<<<(N_EDGES + 255) / 256, 256>>>(eidx + N_EDGES);
    scan_offsets<<<1, 1024>>>();
    scatter_sort<<<(N_EDGES + 255) / 256, 256>>>(eidx, eidx + N_EDGES);

    // h = relu(x @ linW + linB)
    pdense<<<dim3(148, 1), 512, PD_SMEM>>>(x, wpk, linB, hp,
                                           x, wpk, linB, hp,
                                           N_NODES, 128, 1, 1);
    zero_agg_kernel<<<(N_NODES * HID / 4 + 255) / 256, 256>>>();

    for (int l = 0; l < N_LAYERS; l++) {
        // P = h @ W1h + b1
        pdense<<<dim3(148, 1), 512, PD_SMEM>>>(
            hp, wpk + (size_t)(1 + l) * SLAB_WORDS, b1 + l * 128, pp,
            hp, wpk + (size_t)(1 + l) * SLAB_WORDS, b1 + l * 128, pp,
            N_NODES, 128, 1, 0);
        // edge MLP + segmented scatter into agg (dst-sorted)
        edge_kernel<<<148, 512, EDGE_SMEM>>>(
            eattr,
            wpk + (size_t)25 * SLAB_WORDS + (size_t)l * W1E_WORDS,
            wpk + (size_t)(22 + l) * SLAB_WORDS,
            b2 + l * 128);
        // gi = agg @ wihT + bih  |  gh = h @ whhT + bhh  (single wave)
        pdense<<<dim3(24, 6), 512, PD_SMEM>>>(
            aggp, wpk + (size_t)(4 + 3 * l) * SLAB_WORDS, bih + l * 384, gip,
            hp,   wpk + (size_t)(13 + 3 * l) * SLAB_WORDS, bhh + l * 384, ghp,
            N_NODES, 384, 3, 0);
        gru_epi_kernel<<<(N_NODES * HID + 255) / 256, 256>>>(
            bng + l * 128, bnb + l * 128, bnm + l * 128, bnv + l * 128);
    }

    zero_readout_kernel<<<(N_GRAPHS * HID + 255) / 256, 256>>>();
    readout_acc_kernel<<<(N_NODES + 127) / 128, 128>>>(batch);
    readout_final_kernel<<<N_GRAPHS, HID>>>(roW, roB, out);
}

// round 12
// speedup vs baseline: 1.9315x; 1.9315x over previous
#include <cuda_runtime.h>
#include <math.h>
#include <stdint.h>

#define N_NODES   50000
#define N_EDGES   800000
#define IN_DIM    128
#define EDGE_DIM  16
#define HID       128
#define N_LAYERS  3
#define N_GRAPHS  256
#define BN_EPS    1e-5f

// fragment-major weight layout (R6-proven)
#define FRAG_PITCH 260
#define SLAB_WORDS (64 * FRAG_PITCH)   // 16640 (K=128 slab)
#define W1E_WORDS  (8 * FRAG_PITCH)    // 2080  (K=16 slab)

// ---------------- scratch ----------------
__device__ float    g_h[N_NODES * HID];
__device__ float    g_agg[N_NODES * HID];     // per-node Σ hidden (128-dim)
__device__ float    g_p[N_NODES * HID];
__device__ float    g_gi[N_NODES * 3 * HID];
__device__ float    g_gh[N_NODES * 3 * HID];
__device__ unsigned g_wpack[25 * SLAB_WORDS + 3 * W1E_WORDS];
__device__ unsigned g_wfpk[9 * SLAB_WORDS];   // Wfused = W2 @ wihT, packed
__device__ float    g_bf[3 * 384];            // bf = wih @ b2
__device__ int      g_degi[N_NODES];
__device__ float    g_rsum[N_GRAPHS * HID];
__device__ unsigned g_rmax[N_GRAPHS * HID];
__device__ int      g_rcnt[N_GRAPHS];

// ---------------- helpers ----------------
__device__ __forceinline__ unsigned fenc(float f) {
    unsigned u = __float_as_uint(f);
    return (u & 0x80000000u) ? ~u : (u | 0x80000000u);
}
__device__ __forceinline__ float fdec(unsigned k) {
    return __uint_as_float((k & 0x80000000u) ? (k & 0x7fffffffu) : ~k);
}
__device__ __forceinline__ unsigned f2tf(float f) {
    unsigned u;
    asm("cvt.rna.tf32.f32 %0, %1;" : "=r"(u) : "f"(f));
    return u;
}
__device__ __forceinline__ void mma_tf32(float* c, const unsigned* a,
                                         unsigned b0, unsigned b1) {
    asm volatile(
        "mma.sync.aligned.m16n8k8.row.col.f32.tf32.tf32.f32 "
        "{%0,%1,%2,%3}, {%4,%5,%6,%7}, {%8,%9}, {%0,%1,%2,%3};"
        : "+f"(c[0]), "+f"(c[1]), "+f"(c[2]), "+f"(c[3])
        : "r"(a[0]), "r"(a[1]), "r"(a[2]), "r"(a[3]), "r"(b0), "r"(b1));
}
__device__ __forceinline__ void cp16(uint32_t s, const void* g) {
    asm volatile("cp.async.cg.shared.global [%0], [%1], 16;" :: "r"(s), "l"(g));
}
__device__ __forceinline__ void red2(float* p, float a, float b) {
    asm volatile("red.global.add.v2.f32 [%0], {%1,%2};"
                 :: "l"(p), "f"(a), "f"(b) : "memory");
}
__device__ __forceinline__ int frag_off(int ks, int tg, int wn, int gid,
                                        int nt, int pair) {
    return (ks * 4 + tg) * FRAG_PITCH + ((wn * 8 + gid) * 8 + nt) * 2 + pair;
}

// ---------------- weight pre-pack ----------------
__global__ void pack_all(const float* __restrict__ linW,
                         const float* __restrict__ w1,
                         const float* __restrict__ wih,
                         const float* __restrict__ whh,
                         const float* __restrict__ w2) {
    int idx = blockIdx.x * blockDim.x + threadIdx.x;
    const int NMAIN = 25 * 16384;
    if (idx < NMAIN) {
        int slab = idx >> 14, r = idx & 16383;
        int pair = r & 1, nt = (r >> 1) & 7, gid = (r >> 4) & 7;
        int wn = (r >> 7) & 1, tg = (r >> 8) & 3, ks = r >> 10;
        int row = ks * 8 + tg + pair * 4;
        int col = wn * 64 + nt * 8 + gid;
        float v;
        if (slab == 0)      v = linW[row * 128 + col];
        else if (slab < 4)  { int l = slab - 1;
            v = w1[(size_t)l * 144 * 128 + row * 128 + col]; }
        else if (slab < 13) { int t = slab - 4, l = t / 3, j = t % 3;
            v = wih[(size_t)l * 384 * 128 + (size_t)(j * 128 + col) * 128 + row]; }
        else if (slab < 22) { int t = slab - 13, l = t / 3, j = t % 3;
            v = whh[(size_t)l * 384 * 128 + (size_t)(j * 128 + col) * 128 + row]; }
        else                { int l = slab - 22;
            v = w2[(size_t)l * 128 * 128 + row * 128 + col]; }
        g_wpack[slab * SLAB_WORDS + frag_off(ks, tg, wn, gid, nt, pair)] = f2tf(v);
    } else {
        int r2 = idx - NMAIN;
        if (r2 >= 3 * 2048) return;
        int l = r2 >> 11, r = r2 & 2047;
        int pair = r & 1, nt = (r >> 1) & 7, gid = (r >> 4) & 7;
        int wn = (r >> 7) & 1, tg = (r >> 8) & 3, ks = r >> 10;
        int row = ks * 8 + tg + pair * 4;
        int col = wn * 64 + nt * 8 + gid;
        float v = w1[(size_t)l * 144 * 128 + (size_t)(128 + row) * 128 + col];
        g_wpack[25 * SLAB_WORDS + l * W1E_WORDS
                + frag_off(ks, tg, wn, gid, nt, pair)] = f2tf(v);
    }
}

// ---------------- fused weight: Wfused[l][k][o] = sum_j W2[l][k][j]*wih[l][o][j]
// + bf[l][o] = sum_j wih[l][o][j]*b2[l][j]
__global__ void wfuse_kernel(const float* __restrict__ w2,
                             const float* __restrict__ wih,
                             const float* __restrict__ b2) {
    int idx = blockIdx.x * blockDim.x + threadIdx.x;
    const int NF = 9 * 16384;
    if (idx < NF) {
        int sl = idx >> 14, r = idx & 16383;
        int l = sl / 3, js = sl % 3;
        int pair = r & 1, nt = (r >> 1) & 7, gid = (r >> 4) & 7;
        int wn = (r >> 7) & 1, tg = (r >> 8) & 3, ks = r >> 10;
        int row = ks * 8 + tg + pair * 4;         // k index
        int col = wn * 64 + nt * 8 + gid;         // o within slab
        int og = js * 128 + col;                  // global o (0..383)
        const float* w2r = w2 + (size_t)l * 16384 + row * 128;
        const float* wir = wih + (size_t)l * 49152 + (size_t)og * 128;
        float s = 0.f;
#pragma unroll 8
        for (int j = 0; j < 128; j++)
            s += __uint_as_float(f2tf(__ldg(w2r + j)))
               * __uint_as_float(f2tf(__ldg(wir + j)));
        g_wfpk[(size_t)sl * SLAB_WORDS + frag_off(ks, tg, wn, gid, nt, pair)] = f2tf(s);
    } else {
        int r2 = idx - NF;
        if (r2 >= 3 * 384) return;
        int l = r2 / 384, o = r2 % 384;
        const float* wir = wih + (size_t)l * 49152 + (size_t)o * 128;
        const float* b2r = b2 + l * 128;
        float s = 0.f;
        for (int j = 0; j < 128; j++) s += __ldg(wir + j) * __ldg(b2r + j);
        g_bf[l * 384 + o] = s;
    }
}

// ---------------- degree histogram ----------------
__global__ void deg_zero() {
    int i = blockIdx.x * blockDim.x + threadIdx.x;
    if (i < N_NODES) g_degi[i] = 0;
}
__global__ void deg_build(const int* __restrict__ dst) {
    int e = blockIdx.x * blockDim.x + threadIdx.x;
    if (e < N_EDGES) atomicAdd(&g_degi[dst[e]], 1);
}

// ---------------- zero ----------------
__global__ void zero_agg_kernel() {
    int i = blockIdx.x * blockDim.x + threadIdx.x;
    if (i < (N_NODES * HID) / 4)
        ((float4*)g_agg)[i] = make_float4(0.f, 0.f, 0.f, 0.f);
}
__global__ void zero_readout_kernel() {
    int i = blockIdx.x * blockDim.x + threadIdx.x;
    if (i < N_GRAPHS * HID) { g_rsum[i] = 0.f; g_rmax[i] = 0u; }
    if (i < N_GRAPHS) g_rcnt[i] = 0;
}

// ---------------- persistent dense tf32 GEMM, 512 threads ----------------
#define PD_WORDS (SLAB_WORDS + 2 * 128 * 132)
#define PD_SMEM  (PD_WORDS * 4)
__global__ void __launch_bounds__(512)
pdense(const float* __restrict__ Aa, const unsigned* __restrict__ pka,
       const float* __restrict__ biasa, float* __restrict__ Ca,
       const float* __restrict__ Ab, const unsigned* __restrict__ pkb,
       const float* __restrict__ biasb, float* __restrict__ Cb,
       int M, int nC, int nslabA, int relu) {
    extern __shared__ unsigned psm[];
    unsigned* sB = psm;
    float*    sA = (float*)(psm + SLAB_WORDS);
    int slab = blockIdx.y;
    const float *A, *bias; float* C; const unsigned* wp; int n0;
    if (slab < nslabA) { A = Aa; bias = biasa; C = Ca;
        wp = pka + (size_t)slab * SLAB_WORDS; n0 = slab * 128; }
    else { A = Ab; bias = biasb; C = Cb;
        wp = pkb + (size_t)(slab - nslabA) * SLAB_WORDS; n0 = (slab - nslabA) * 128; }

    int tid = threadIdx.x, lane = tid & 31, wid = tid >> 5;
    int wm = wid & 7, wn = wid >> 3, gid = lane >> 2, tg = lane & 3;
    int r4 = tid >> 2, q = tid & 3;
    uint32_t sa_u32 = (uint32_t)__cvta_generic_to_shared(sA);
    uint32_t sb_u32 = (uint32_t)__cvta_generic_to_shared(sB);

    const int tiles = (M + 127) >> 7;
    for (int i = tid; i < SLAB_WORDS / 4; i += 512)
        cp16(sb_u32 + i * 16, wp + i * 4);
    {
        int gm = blockIdx.x * 128 + r4; if (gm >= M) gm = M - 1;
        const float* ar = A + (size_t)gm * 128 + q * 32;
        uint32_t sa = sa_u32 + (r4 * 132 + q * 32) * 4;
#pragma unroll
        for (int k = 0; k < 8; k++) cp16(sa + k * 16, ar + k * 4);
    }
    asm volatile("cp.async.commit_group;");

    int buf = 0;
    for (int t = blockIdx.x; t < tiles; t += gridDim.x) {
        int tn = t + gridDim.x;
        if (tn < tiles) {
            int gm = tn * 128 + r4; if (gm >= M) gm = M - 1;
            const float* ar = A + (size_t)gm * 128 + q * 32;
            uint32_t sa = sa_u32 + ((buf ^ 1) * 128 * 132 + r4 * 132 + q * 32) * 4;
#pragma unroll
            for (int k = 0; k < 8; k++) cp16(sa + k * 16, ar + k * 4);
        }
        asm volatile("cp.async.commit_group;");
        asm volatile("cp.async.wait_group 1;");
        __syncthreads();

        const unsigned* sAu = (const unsigned*)(sA + buf * 128 * 132);
        float acc[8][4];
#pragma unroll
        for (int nt = 0; nt < 8; nt++)
#pragma unroll
            for (int i = 0; i < 4; i++) acc[nt][i] = 0.f;

        int R = wm * 16 + gid;
        int bbase = (wn * 8 + gid) * 16;
#pragma unroll 4
        for (int ks = 0; ks < 16; ks++) {
            unsigned a[4];
            int col = ks * 8 + tg;
            a[0] = sAu[R * 132 + col];
            a[1] = sAu[(R + 8) * 132 + col];
            a[2] = sAu[R * 132 + col + 4];
            a[3] = sAu[(R + 8) * 132 + col + 4];
            const uint4* bp = (const uint4*)(sB + (ks * 4 + tg) * FRAG_PITCH + bbase);
#pragma unroll
            for (int j = 0; j < 4; j++) {
                uint4 b = bp[j];
                mma_tf32(acc[2 * j],     a, b.x, b.y);
                mma_tf32(acc[2 * j + 1], a, b.z, b.w);
            }
        }

        int m0 = t * 128;
#pragma unroll
        for (int nt = 0; nt < 8; nt++)
#pragma unroll
            for (int p = 0; p < 2; p++) {
                int gm = m0 + R + p * 8;
                if (gm < M) {
                    int col = wn * 64 + nt * 8 + 2 * tg;
                    float2 v;
                    v.x = acc[nt][p * 2]     + __ldg(bias + n0 + col);
                    v.y = acc[nt][p * 2 + 1] + __ldg(bias + n0 + col + 1);
                    if (relu) { v.x = fmaxf(v.x, 0.f); v.y = fmaxf(v.y, 0.f); }
                    *(float2*)(C + (size_t)gm * nC + n0 + col) = v;
                }
            }
        __syncthreads();
        buf ^= 1;
    }
}

// ---------------- edge kernel: hidden = relu(P[src] + e@W1e) -> scatter ----
#define EW_W1E  0
#define EW_A    W1E_WORDS                     // 2080 : 2 bufs of 128x132
#define EW_E    (EW_A + 2 * 128 * 132)        // 35872 : 2 bufs of 128x16
#define EDGE_WORDS (EW_E + 2 * 128 * 16)      // 39968
#define EDGE_SMEM (EDGE_WORDS * 4)            // 159872 B

__global__ void __launch_bounds__(512)
edge_kernel(const float* __restrict__ eattr,
            const int* __restrict__ src,
            const int* __restrict__ dst,
            const unsigned* __restrict__ W1epk) {
    extern __shared__ unsigned smu[];
    unsigned* sW1e = smu + EW_W1E;
    float*    smf  = (float*)smu;
    uint32_t smem_u32 = (uint32_t)__cvta_generic_to_shared(smu);

    int tid = threadIdx.x, lane = tid & 31, wid = tid >> 5;
    int wm = wid & 7, wn = wid >> 3, gid = lane >> 2, tg = lane & 3;
    int r4 = tid >> 2, q = tid & 3;

    // prologue: W1e + first P/E gather, one cp.async group
    for (int i = tid; i < W1E_WORDS / 4; i += 512)
        cp16(smem_u32 + i * 16, W1epk + i * 4);
    {
        int e0 = blockIdx.x * 128;
        int s = __ldg(src + e0 + r4);
        const float* pr = g_p + (size_t)s * HID + q * 32;
        uint32_t sa = smem_u32 + (EW_A + r4 * 132 + q * 32) * 4;
#pragma unroll
        for (int k = 0; k < 8; k++) cp16(sa + k * 16, pr + k * 4);
        const float* er = eattr + (size_t)(e0 + r4) * EDGE_DIM + q * 4;
        cp16(smem_u32 + (EW_E + r4 * 16 + q * 4) * 4, er);
    }
    asm volatile("cp.async.commit_group;");

    const int ntiles = N_EDGES / 128;  // 6250
    int buf = 0;
    for (int t = blockIdx.x; t < ntiles; t += gridDim.x) {
        int tn = t + gridDim.x;
        if (tn < ntiles) {  // prefetch next tile into buf^1
            int e0n = tn * 128;
            int s = __ldg(src + e0n + r4);
            const float* pr = g_p + (size_t)s * HID + q * 32;
            uint32_t sa = smem_u32 + (EW_A + (buf ^ 1) * (128 * 132) + r4 * 132 + q * 32) * 4;
#pragma unroll
            for (int k = 0; k < 8; k++) cp16(sa + k * 16, pr + k * 4);
            const float* er = eattr + (size_t)(e0n + r4) * EDGE_DIM + q * 4;
            cp16(smem_u32 + (EW_E + (buf ^ 1) * (128 * 16) + r4 * 16 + q * 4) * 4, er);
        }
        asm volatile("cp.async.commit_group;");
        asm volatile("cp.async.wait_group 1;");
        __syncthreads();

        float*    sAf = smf + EW_A + buf * (128 * 132);
        unsigned* sEu = smu + EW_E + buf * (128 * 16);
        int e0 = t * 128;
        int R = wm * 16 + gid;
        int bbase = (wn * 8 + gid) * 16;

        // acc = P[src] (fp32) + eattr @ W1e (K=16)
        float acc[8][4];
#pragma unroll
        for (int nt = 0; nt < 8; nt++) {
            int Cc = wn * 64 + nt * 8 + 2 * tg;
            float2 v0 = *(float2*)(sAf + R * 132 + Cc);
            float2 v1 = *(float2*)(sAf + (R + 8) * 132 + Cc);
            acc[nt][0] = v0.x; acc[nt][1] = v0.y;
            acc[nt][2] = v1.x; acc[nt][3] = v1.y;
        }
#pragma unroll
        for (int ks = 0; ks < 2; ks++) {
            unsigned a[4];
            int col = ks * 8 + tg;
            a[0] = sEu[R * 16 + col];
            a[1] = sEu[(R + 8) * 16 + col];
            a[2] = sEu[R * 16 + col + 4];
            a[3] = sEu[(R + 8) * 16 + col + 4];
            const uint4* bp = (const uint4*)(sW1e + (ks * 4 + tg) * FRAG_PITCH + bbase);
#pragma unroll
            for (int j = 0; j < 4; j++) {
                uint4 b = bp[j];
                mma_tf32(acc[2 * j],     a, b.x, b.y);
                mma_tf32(acc[2 * j + 1], a, b.z, b.w);
            }
        }
        __syncthreads();  // all reads of buf done before next prefetch overwrites

        // relu + scatter hidden into g_agg[dst]
        int d0 = __ldg(dst + e0 + R);
        int d1 = __ldg(dst + e0 + R + 8);
#pragma unroll
        for (int nt = 0; nt < 8; nt++) {
            int col = wn * 64 + nt * 8 + 2 * tg;
            red2(&g_agg[(size_t)d0 * HID + col],
                 fmaxf(acc[nt][0], 0.f), fmaxf(acc[nt][1], 0.f));
            red2(&g_agg[(size_t)d1 * HID + col],
                 fmaxf(acc[nt][2], 0.f), fmaxf(acc[nt][3], 0.f));
        }
        buf ^= 1;
    }
}

// ---------------- GRU gates + BN + residual (+ deg*bf, + zero agg) --------
__global__ void gru_epi_kernel(const float* __restrict__ gamma,
                               const float* __restrict__ beta,
                               const float* __restrict__ mean,
                               const float* __restrict__ var,
                               const float* __restrict__ bf) {
    int idx = blockIdx.x * blockDim.x + threadIdx.x;
    if (idx >= N_NODES * HID) return;
    int n = idx >> 7, j = idx & 127;
    const float* gi = g_gi + (size_t)n * 384;
    const float* gh = g_gh + (size_t)n * 384;
    float dg = (float)g_degi[n];
    float ir = gi[j]       + dg * bf[j];
    float iz = gi[128 + j] + dg * bf[128 + j];
    float inn = gi[256 + j] + dg * bf[256 + j];
    float hr = gh[j], hz = gh[128 + j], hn = gh[256 + j];
    float h = g_h[idx];
    float r = 1.f / (1.f + __expf(-(ir + hr)));
    float z = 1.f / (1.f + __expf(-(iz + hz)));
    float nn = tanhf(inn + r * hn);
    float hnew = (1.f - z) * nn + z * h;
    float bn = (hnew - mean[j]) * rsqrtf(var[j] + BN_EPS) * gamma[j] + beta[j];
    g_h[idx] = h + bn;
    g_agg[idx] = 0.f;
}

// ---------------- readout ----------------
__global__ void readout_acc_kernel(const int* __restrict__ batch) {
    __shared__ int sb[128];
    int j = threadIdx.x;
    int nBeg = blockIdx.x * 128;
    int cnt = min(128, N_NODES - nBeg);
    sb[j] = (j < cnt) ? __ldg(batch + nBeg + j) : -1;
    __syncthreads();
    int curb = sb[0];
    float s = 0.f; unsigned mx = 0u; int c = 0;
    for (int i = 0; i < cnt; i++) {
        int b = sb[i];
        float v = g_h[(size_t)(nBeg + i) * HID + j];
        if (b != curb) {
            atomicAdd(&g_rsum[curb * HID + j], s);
            atomicMax(&g_rmax[curb * HID + j], mx);
            if (j == 0) atomicAdd(&g_rcnt[curb], c);
            s = 0.f; mx = 0u; c = 0; curb = b;
        }
        s += v; mx = max(mx, fenc(v)); c++;
    }
    if (c > 0) {
        atomicAdd(&g_rsum[curb * HID + j], s);
        atomicMax(&g_rmax[curb * HID + j], mx);
        if (j == 0) atomicAdd(&g_rcnt[curb], c);
    }
}
__global__ void readout_final_kernel(const float* __restrict__ roW,
                                     const float* __restrict__ roB,
                                     float* __restrict__ out) {
    __shared__ float s[2 * HID];
    int g = blockIdx.x, j = threadIdx.x;
    int cnt = g_rcnt[g];
    float mv = g_rsum[g * HID + j] / fmaxf((float)cnt, 1.f);
    float xv = (cnt > 0) ? fdec(g_rmax[g * HID + j]) : 0.f;
    s[j] = mv;
    s[HID + j] = xv;
    __syncthreads();
    float acc = roB[j];
    for (int k = 0; k < 2 * HID; k++) acc += s[k] * roW[k * HID + j];
    out[g * HID + j] = fmaxf(acc, 0.f);
}

// ---------------- launch ----------------
extern "C" void kernel_launch(void* const* d_in, const int* in_sizes, int n_in,
                              void* d_out, int out_size) {
    int base = (in_sizes[4] <= 2) ? 5 : 4;
    const float* x     = (const float*)d_in[0];
    const int*   eidx  = (const int*)d_in[1];
    const float* eattr = (const float*)d_in[2];
    const int*   batch = (const int*)d_in[3];
    const float* linW  = (const float*)d_in[base + 0];
    const float* linB  = (const float*)d_in[base + 1];
    const float* w1    = (const float*)d_in[base + 2];
    const float* b1    = (const float*)d_in[base + 3];
    const float* w2    = (const float*)d_in[base + 4];
    const float* b2    = (const float*)d_in[base + 5];
    const float* bng   = (const float*)d_in[base + 6];
    const float* bnb   = (const float*)d_in[base + 7];
    const float* bnm   = (const float*)d_in[base + 8];
    const float* bnv   = (const float*)d_in[base + 9];
    const float* wih   = (const float*)d_in[base + 10];
    const float* whh   = (const float*)d_in[base + 11];
    const float* bih   = (const float*)d_in[base + 12];
    const float* bhh   = (const float*)d_in[base + 13];
    const float* roW   = (const float*)d_in[base + 14];
    const float* roB   = (const float*)d_in[base + 15];
    float* out = (float*)d_out;

    cudaFuncSetAttribute(pdense,      cudaFuncAttributeMaxDynamicSharedMemorySize, PD_SMEM);
    cudaFuncSetAttribute(edge_kernel, cudaFuncAttributeMaxDynamicSharedMemorySize, EDGE_SMEM);

    float *hp, *aggp, *pp, *gip, *ghp, *bfp;
    unsigned *wpk, *wfpk;
    cudaGetSymbolAddress((void**)&hp,   g_h);
    cudaGetSymbolAddress((void**)&aggp, g_agg);
    cudaGetSymbolAddress((void**)&pp,   g_p);
    cudaGetSymbolAddress((void**)&gip,  g_gi);
    cudaGetSymbolAddress((void**)&ghp,  g_gh);
    cudaGetSymbolAddress((void**)&wpk,  g_wpack);
    cudaGetSymbolAddress((void**)&wfpk, g_wfpk);
    cudaGetSymbolAddress((void**)&bfp,  g_bf);

    // one-time setup: packs, fused weights, degree histogram
    pack_all<<<(25 * 16384 + 3 * 2048 + 511) / 512, 512>>>(linW, w1, wih, whh, w2);
    wfuse_kernel<<<(9 * 16384 + 3 * 384 + 255) / 256, 256>>>(w2, wih, b2);
    deg_zero<<<(N_NODES + 255) / 256, 256>>>();
    deg_build<<<(N_EDGES + 255) / 256, 256>>>(eidx + N_EDGES);

    // h = relu(x @ linW + linB)
    pdense<<<dim3(148, 1), 512, PD_SMEM>>>(x, wpk, linB, hp,
                                           x, wpk, linB, hp,
                                           N_NODES, 128, 1, 1);
    zero_agg_kernel<<<(N_NODES * HID / 4 + 255) / 256, 256>>>();

    for (int l = 0; l < N_LAYERS; l++) {
        // P = h @ W1h + b1
        pdense<<<dim3(148, 1), 512, PD_SMEM>>>(
            hp, wpk + (size_t)(1 + l) * SLAB_WORDS, b1 + l * 128, pp,
            hp, wpk + (size_t)(1 + l) * SLAB_WORDS, b1 + l * 128, pp,
            N_NODES, 128, 1, 0);
        // edge: scatter relu(P[src] + e@W1e) into g_agg
        edge_kernel<<<148, 512, EDGE_SMEM>>>(
            eattr, eidx, eidx + N_EDGES,
            wpk + (size_t)25 * SLAB_WORDS + (size_t)l * W1E_WORDS);
        // gi = H_agg @ Wfused + bih   |   gh = h @ whhT + bhh
        pdense<<<dim3(24, 6), 512, PD_SMEM>>>(
            aggp, wfpk + (size_t)(3 * l) * SLAB_WORDS, bih + l * 384, gip,
            hp,   wpk + (size_t)(13 + 3 * l) * SLAB_WORDS, bhh + l * 384, ghp,
            N_NODES, 384, 3, 0);
        gru_epi_kernel<<<(N_NODES * HID + 255) / 256, 256>>>(
            bng + l * 128, bnb + l * 128, bnm + l * 128, bnv + l * 128,
            bfp + l * 384);
    }

    zero_readout_kernel<<<(N_GRAPHS * HID + 255) / 256, 256>>>();
    readout_acc_kernel<<<(N_NODES + 127) / 128, 128>>>(batch);
    readout_final_kernel<<<N_GRAPHS, HID>>>(roW, roB, out);
}

// round 14
// speedup vs baseline: 2.0368x; 1.0545x over previous
#include <cuda_runtime.h>
#include <math.h>
#include <stdint.h>

#define N_NODES   50000
#define N_EDGES   800000
#define IN_DIM    128
#define EDGE_DIM  16
#define HID       128
#define N_LAYERS  3
#define N_GRAPHS  256
#define BN_EPS    1e-5f

// fragment-major weight layout (R6-proven)
#define FRAG_PITCH 260
#define SLAB_WORDS (64 * FRAG_PITCH)   // 16640 (K=128 slab)
#define W1E_WORDS  (8 * FRAG_PITCH)    // 2080  (K=16 slab)

// ---------------- scratch ----------------
__device__ float    g_h[N_NODES * HID];
__device__ float    g_agg[N_NODES * HID];     // per-node Σ hidden (128-dim)
__device__ float    g_p[N_NODES * HID];
__device__ float    g_gi[N_NODES * 3 * HID];
__device__ float    g_gh[N_NODES * 3 * HID];
__device__ unsigned g_wpack[25 * SLAB_WORDS + 3 * W1E_WORDS];
__device__ unsigned g_wfpk[9 * SLAB_WORDS];   // Wfused = W2 @ wihT, packed
__device__ float    g_bf[3 * 384];            // bf = wih @ b2
__device__ int      g_degi[N_NODES];
__device__ float    g_rsum[N_GRAPHS * HID];
__device__ unsigned g_rmax[N_GRAPHS * HID];
__device__ int      g_rcnt[N_GRAPHS];

// ---------------- helpers ----------------
__device__ __forceinline__ unsigned fenc(float f) {
    unsigned u = __float_as_uint(f);
    return (u & 0x80000000u) ? ~u : (u | 0x80000000u);
}
__device__ __forceinline__ float fdec(unsigned k) {
    return __uint_as_float((k & 0x80000000u) ? (k & 0x7fffffffu) : ~k);
}
__device__ __forceinline__ unsigned f2tf(float f) {
    unsigned u;
    asm("cvt.rna.tf32.f32 %0, %1;" : "=r"(u) : "f"(f));
    return u;
}
__device__ __forceinline__ void mma_tf32(float* c, const unsigned* a,
                                         unsigned b0, unsigned b1) {
    asm volatile(
        "mma.sync.aligned.m16n8k8.row.col.f32.tf32.tf32.f32 "
        "{%0,%1,%2,%3}, {%4,%5,%6,%7}, {%8,%9}, {%0,%1,%2,%3};"
        : "+f"(c[0]), "+f"(c[1]), "+f"(c[2]), "+f"(c[3])
        : "r"(a[0]), "r"(a[1]), "r"(a[2]), "r"(a[3]), "r"(b0), "r"(b1));
}
__device__ __forceinline__ void cp16(uint32_t s, const void* g) {
    asm volatile("cp.async.cg.shared.global [%0], [%1], 16;" :: "r"(s), "l"(g));
}
__device__ __forceinline__ void red2(float* p, float a, float b) {
    asm volatile("red.global.add.v2.f32 [%0], {%1,%2};"
                 :: "l"(p), "f"(a), "f"(b) : "memory");
}
__device__ __forceinline__ int frag_off(int ks, int tg, int wn, int gid,
                                        int nt, int pair) {
    return (ks * 4 + tg) * FRAG_PITCH + ((wn * 8 + gid) * 8 + nt) * 2 + pair;
}

// ---------------- weight pre-pack ----------------
__global__ void pack_all(const float* __restrict__ linW,
                         const float* __restrict__ w1,
                         const float* __restrict__ wih,
                         const float* __restrict__ whh,
                         const float* __restrict__ w2) {
    int idx = blockIdx.x * blockDim.x + threadIdx.x;
    const int NMAIN = 25 * 16384;
    if (idx < NMAIN) {
        int slab = idx >> 14, r = idx & 16383;
        int pair = r & 1, nt = (r >> 1) & 7, gid = (r >> 4) & 7;
        int wn = (r >> 7) & 1, tg = (r >> 8) & 3, ks = r >> 10;
        int row = ks * 8 + tg + pair * 4;
        int col = wn * 64 + nt * 8 + gid;
        float v;
        if (slab == 0)      v = linW[row * 128 + col];
        else if (slab < 4)  { int l = slab - 1;
            v = w1[(size_t)l * 144 * 128 + row * 128 + col]; }
        else if (slab < 13) { int t = slab - 4, l = t / 3, j = t % 3;
            v = wih[(size_t)l * 384 * 128 + (size_t)(j * 128 + col) * 128 + row]; }
        else if (slab < 22) { int t = slab - 13, l = t / 3, j = t % 3;
            v = whh[(size_t)l * 384 * 128 + (size_t)(j * 128 + col) * 128 + row]; }
        else                { int l = slab - 22;
            v = w2[(size_t)l * 128 * 128 + row * 128 + col]; }
        g_wpack[slab * SLAB_WORDS + frag_off(ks, tg, wn, gid, nt, pair)] = f2tf(v);
    } else {
        int r2 = idx - NMAIN;
        if (r2 >= 3 * 2048) return;
        int l = r2 >> 11, r = r2 & 2047;
        int pair = r & 1, nt = (r >> 1) & 7, gid = (r >> 4) & 7;
        int wn = (r >> 7) & 1, tg = (r >> 8) & 3, ks = r >> 10;
        int row = ks * 8 + tg + pair * 4;
        int col = wn * 64 + nt * 8 + gid;
        float v = w1[(size_t)l * 144 * 128 + (size_t)(128 + row) * 128 + col];
        g_wpack[25 * SLAB_WORDS + l * W1E_WORDS
                + frag_off(ks, tg, wn, gid, nt, pair)] = f2tf(v);
    }
}

// ---------------- fused weight: Wfused[l][k][o] = sum_j W2[l][k][j]*wih[l][o][j]
__global__ void wfuse_kernel(const float* __restrict__ w2,
                             const float* __restrict__ wih,
                             const float* __restrict__ b2) {
    int idx = blockIdx.x * blockDim.x + threadIdx.x;
    const int NF = 9 * 16384;
    if (idx < NF) {
        int sl = idx >> 14, r = idx & 16383;
        int l = sl / 3, js = sl % 3;
        int pair = r & 1, nt = (r >> 1) & 7, gid = (r >> 4) & 7;
        int wn = (r >> 7) & 1, tg = (r >> 8) & 3, ks = r >> 10;
        int row = ks * 8 + tg + pair * 4;
        int col = wn * 64 + nt * 8 + gid;
        int og = js * 128 + col;
        const float* w2r = w2 + (size_t)l * 16384 + row * 128;
        const float* wir = wih + (size_t)l * 49152 + (size_t)og * 128;
        float s = 0.f;
#pragma unroll 8
        for (int j = 0; j < 128; j++)
            s += __uint_as_float(f2tf(__ldg(w2r + j)))
               * __uint_as_float(f2tf(__ldg(wir + j)));
        g_wfpk[(size_t)sl * SLAB_WORDS + frag_off(ks, tg, wn, gid, nt, pair)] = f2tf(s);
    } else {
        int r2 = idx - NF;
        if (r2 >= 3 * 384) return;
        int l = r2 / 384, o = r2 % 384;
        const float* wir = wih + (size_t)l * 49152 + (size_t)o * 128;
        const float* b2r = b2 + l * 128;
        float s = 0.f;
        for (int j = 0; j < 128; j++) s += __ldg(wir + j) * __ldg(b2r + j);
        g_bf[l * 384 + o] = s;
    }
}

// ---------------- degree histogram ----------------
__global__ void deg_zero() {
    int i = blockIdx.x * blockDim.x + threadIdx.x;
    if (i < N_NODES) g_degi[i] = 0;
}
__global__ void deg_build(const int* __restrict__ dst) {
    int e = blockIdx.x * blockDim.x + threadIdx.x;
    if (e < N_EDGES) atomicAdd(&g_degi[dst[e]], 1);
}

// ---------------- zero ----------------
__global__ void zero_agg_kernel() {
    int i = blockIdx.x * blockDim.x + threadIdx.x;
    if (i < (N_NODES * HID) / 4)
        ((float4*)g_agg)[i] = make_float4(0.f, 0.f, 0.f, 0.f);
}
__global__ void zero_readout_kernel() {
    int i = blockIdx.x * blockDim.x + threadIdx.x;
    if (i < N_GRAPHS * HID) { g_rsum[i] = 0.f; g_rmax[i] = 0u; }
    if (i < N_GRAPHS) g_rcnt[i] = 0;
}

// ---------------- persistent dense tf32 GEMM, 512 threads ----------------
#define PD_WORDS (SLAB_WORDS + 2 * 128 * 132)
#define PD_SMEM  (PD_WORDS * 4)
__global__ void __launch_bounds__(512)
pdense(const float* __restrict__ Aa, const unsigned* __restrict__ pka,
       const float* __restrict__ biasa, float* __restrict__ Ca,
       const float* __restrict__ Ab, const unsigned* __restrict__ pkb,
       const float* __restrict__ biasb, float* __restrict__ Cb,
       int M, int nC, int nslabA, int relu) {
    extern __shared__ unsigned psm[];
    unsigned* sB = psm;
    float*    sA = (float*)(psm + SLAB_WORDS);
    int slab = blockIdx.y;
    const float *A, *bias; float* C; const unsigned* wp; int n0;
    if (slab < nslabA) { A = Aa; bias = biasa; C = Ca;
        wp = pka + (size_t)slab * SLAB_WORDS; n0 = slab * 128; }
    else { A = Ab; bias = biasb; C = Cb;
        wp = pkb + (size_t)(slab - nslabA) * SLAB_WORDS; n0 = (slab - nslabA) * 128; }

    int tid = threadIdx.x, lane = tid & 31, wid = tid >> 5;
    int wm = wid & 7, wn = wid >> 3, gid = lane >> 2, tg = lane & 3;
    int r4 = tid >> 2, q = tid & 3;
    uint32_t sa_u32 = (uint32_t)__cvta_generic_to_shared(sA);
    uint32_t sb_u32 = (uint32_t)__cvta_generic_to_shared(sB);

    const int tiles = (M + 127) >> 7;
    for (int i = tid; i < SLAB_WORDS / 4; i += 512)
        cp16(sb_u32 + i * 16, wp + i * 4);
    {
        int gm = blockIdx.x * 128 + r4; if (gm >= M) gm = M - 1;
        const float* ar = A + (size_t)gm * 128 + q * 32;
        uint32_t sa = sa_u32 + (r4 * 132 + q * 32) * 4;
#pragma unroll
        for (int k = 0; k < 8; k++) cp16(sa + k * 16, ar + k * 4);
    }
    asm volatile("cp.async.commit_group;");

    int buf = 0;
    for (int t = blockIdx.x; t < tiles; t += gridDim.x) {
        int tn = t + gridDim.x;
        if (tn < tiles) {
            int gm = tn * 128 + r4; if (gm >= M) gm = M - 1;
            const float* ar = A + (size_t)gm * 128 + q * 32;
            uint32_t sa = sa_u32 + ((buf ^ 1) * 128 * 132 + r4 * 132 + q * 32) * 4;
#pragma unroll
            for (int k = 0; k < 8; k++) cp16(sa + k * 16, ar + k * 4);
        }
        asm volatile("cp.async.commit_group;");
        asm volatile("cp.async.wait_group 1;");
        __syncthreads();

        const unsigned* sAu = (const unsigned*)(sA + buf * 128 * 132);
        float acc[8][4];
#pragma unroll
        for (int nt = 0; nt < 8; nt++)
#pragma unroll
            for (int i = 0; i < 4; i++) acc[nt][i] = 0.f;

        int R = wm * 16 + gid;
        int bbase = (wn * 8 + gid) * 16;
#pragma unroll 4
        for (int ks = 0; ks < 16; ks++) {
            unsigned a[4];
            int col = ks * 8 + tg;
            a[0] = sAu[R * 132 + col];
            a[1] = sAu[(R + 8) * 132 + col];
            a[2] = sAu[R * 132 + col + 4];
            a[3] = sAu[(R + 8) * 132 + col + 4];
            const uint4* bp = (const uint4*)(sB + (ks * 4 + tg) * FRAG_PITCH + bbase);
#pragma unroll
            for (int j = 0; j < 4; j++) {
                uint4 b = bp[j];
                mma_tf32(acc[2 * j],     a, b.x, b.y);
                mma_tf32(acc[2 * j + 1], a, b.z, b.w);
            }
        }

        int m0 = t * 128;
#pragma unroll
        for (int nt = 0; nt < 8; nt++)
#pragma unroll
            for (int p = 0; p < 2; p++) {
                int gm = m0 + R + p * 8;
                if (gm < M) {
                    int col = wn * 64 + nt * 8 + 2 * tg;
                    float2 v;
                    v.x = acc[nt][p * 2]     + __ldg(bias + n0 + col);
                    v.y = acc[nt][p * 2 + 1] + __ldg(bias + n0 + col + 1);
                    if (relu) { v.x = fmaxf(v.x, 0.f); v.y = fmaxf(v.y, 0.f); }
                    *(float2*)(C + (size_t)gm * nC + n0 + col) = v;
                }
            }
        __syncthreads();
        buf ^= 1;
    }
}

// ---------------- edge kernel: BM=64, 256 threads, 2 CTAs/SM --------------
// hidden = relu(P[src] + e@W1e) scattered into g_agg via red2.
#define EBM     64
#define EW_W1E  0
#define EW_E    W1E_WORDS                       // 2080 : 2 bufs of 64x16
#define EW_A    (EW_E + 2 * EBM * 16)           // 4128 : 2 bufs of 64x132
#define EDGE_WORDS (EW_A + 2 * EBM * 132)       // 21024
#define EDGE_SMEM (EDGE_WORDS * 4)              // 84096 B -> 2 CTAs/SM

__global__ void __launch_bounds__(256)
edge_kernel(const float* __restrict__ eattr,
            const int* __restrict__ src,
            const int* __restrict__ dst,
            const unsigned* __restrict__ W1epk) {
    extern __shared__ unsigned smu[];
    unsigned* sW1e = smu + EW_W1E;
    float*    smf  = (float*)smu;
    uint32_t smem_u32 = (uint32_t)__cvta_generic_to_shared(smu);

    int tid = threadIdx.x, lane = tid & 31, wid = tid >> 5;
    int wm = wid & 3, wn = wid >> 2, gid = lane >> 2, tg = lane & 3;
    int r4 = tid >> 2, q = tid & 3;   // r4: 0..63 rows, q: quarter of a row

    // prologue: W1e + first P/E gather, one cp.async group
    for (int i = tid; i < W1E_WORDS / 4; i += 256)
        cp16(smem_u32 + i * 16, W1epk + i * 4);
    {
        int e0 = blockIdx.x * EBM;
        int s = __ldg(src + e0 + r4);
        const float* pr = g_p + (size_t)s * HID + q * 32;
        uint32_t sa = smem_u32 + (EW_A + r4 * 132 + q * 32) * 4;
#pragma unroll
        for (int k = 0; k < 8; k++) cp16(sa + k * 16, pr + k * 4);
        const float* er = eattr + (size_t)(e0 + r4) * EDGE_DIM + q * 4;
        cp16(smem_u32 + (EW_E + r4 * 16 + q * 4) * 4, er);
    }
    asm volatile("cp.async.commit_group;");

    const int ntiles = N_EDGES / EBM;  // 12500
    int buf = 0;
    for (int t = blockIdx.x; t < ntiles; t += gridDim.x) {
        int tn = t + gridDim.x;
        if (tn < ntiles) {  // prefetch next tile into buf^1
            int e0n = tn * EBM;
            int s = __ldg(src + e0n + r4);
            const float* pr = g_p + (size_t)s * HID + q * 32;
            uint32_t sa = smem_u32 + (EW_A + (buf ^ 1) * (EBM * 132) + r4 * 132 + q * 32) * 4;
#pragma unroll
            for (int k = 0; k < 8; k++) cp16(sa + k * 16, pr + k * 4);
            const float* er = eattr + (size_t)(e0n + r4) * EDGE_DIM + q * 4;
            cp16(smem_u32 + (EW_E + (buf ^ 1) * (EBM * 16) + r4 * 16 + q * 4) * 4, er);
        }
        asm volatile("cp.async.commit_group;");
        asm volatile("cp.async.wait_group 1;");
        __syncthreads();

        float*    sAf = smf + EW_A + buf * (EBM * 132);
        unsigned* sEu = smu + EW_E + buf * (EBM * 16);
        int e0 = t * EBM;
        int R = wm * 16 + gid;                  // 0..63 with +8 sibling
        int bbase = (wn * 8 + gid) * 16;

        // acc = P[src] (fp32) + eattr @ W1e (K=16)
        float acc[8][4];
#pragma unroll
        for (int nt = 0; nt < 8; nt++) {
            int Cc = wn * 64 + nt * 8 + 2 * tg;
            float2 v0 = *(float2*)(sAf + R * 132 + Cc);
            float2 v1 = *(float2*)(sAf + (R + 8) * 132 + Cc);
            acc[nt][0] = v0.x; acc[nt][1] = v0.y;
            acc[nt][2] = v1.x; acc[nt][3] = v1.y;
        }
#pragma unroll
        for (int ks = 0; ks < 2; ks++) {
            unsigned a[4];
            int col = ks * 8 + tg;
            a[0] = sEu[R * 16 + col];
            a[1] = sEu[(R + 8) * 16 + col];
            a[2] = sEu[R * 16 + col + 4];
            a[3] = sEu[(R + 8) * 16 + col + 4];
            const uint4* bp = (const uint4*)(sW1e + (ks * 4 + tg) * FRAG_PITCH + bbase);
#pragma unroll
            for (int j = 0; j < 4; j++) {
                uint4 b = bp[j];
                mma_tf32(acc[2 * j],     a, b.x, b.y);
                mma_tf32(acc[2 * j + 1], a, b.z, b.w);
            }
        }
        __syncthreads();  // all reads of buf done before next prefetch overwrites

        // relu + scatter hidden into g_agg[dst]
        int d0 = __ldg(dst + e0 + R);
        int d1 = __ldg(dst + e0 + R + 8);
#pragma unroll
        for (int nt = 0; nt < 8; nt++) {
            int col = wn * 64 + nt * 8 + 2 * tg;
            red2(&g_agg[(size_t)d0 * HID + col],
                 fmaxf(acc[nt][0], 0.f), fmaxf(acc[nt][1], 0.f));
            red2(&g_agg[(size_t)d1 * HID + col],
                 fmaxf(acc[nt][2], 0.f), fmaxf(acc[nt][3], 0.f));
        }
        buf ^= 1;
    }
}

// ---------------- GRU gates + BN + residual (+ deg*bf, + zero agg) --------
__global__ void gru_epi_kernel(const float* __restrict__ gamma,
                               const float* __restrict__ beta,
                               const float* __restrict__ mean,
                               const float* __restrict__ var,
                               const float* __restrict__ bf) {
    int idx = blockIdx.x * blockDim.x + threadIdx.x;
    if (idx >= N_NODES * HID) return;
    int n = idx >> 7, j = idx & 127;
    const float* gi = g_gi + (size_t)n * 384;
    const float* gh = g_gh + (size_t)n * 384;
    float dg = (float)g_degi[n];
    float ir = gi[j]       + dg * bf[j];
    float iz = gi[128 + j] + dg * bf[128 + j];
    float inn = gi[256 + j] + dg * bf[256 + j];
    float hr = gh[j], hz = gh[128 + j], hn = gh[256 + j];
    float h = g_h[idx];
    float r = 1.f / (1.f + __expf(-(ir + hr)));
    float z = 1.f / (1.f + __expf(-(iz + hz)));
    float nn = tanhf(inn + r * hn);
    float hnew = (1.f - z) * nn + z * h;
    float bn = (hnew - mean[j]) * rsqrtf(var[j] + BN_EPS) * gamma[j] + beta[j];
    g_h[idx] = h + bn;
    g_agg[idx] = 0.f;
}

// ---------------- readout ----------------
__global__ void readout_acc_kernel(const int* __restrict__ batch) {
    __shared__ int sb[128];
    int j = threadIdx.x;
    int nBeg = blockIdx.x * 128;
    int cnt = min(128, N_NODES - nBeg);
    sb[j] = (j < cnt) ? __ldg(batch + nBeg + j) : -1;
    __syncthreads();
    int curb = sb[0];
    float s = 0.f; unsigned mx = 0u; int c = 0;
    for (int i = 0; i < cnt; i++) {
        int b = sb[i];
        float v = g_h[(size_t)(nBeg + i) * HID + j];
        if (b != curb) {
            atomicAdd(&g_rsum[curb * HID + j], s);
            atomicMax(&g_rmax[curb * HID + j], mx);
            if (j == 0) atomicAdd(&g_rcnt[curb], c);
            s = 0.f; mx = 0u; c = 0; curb = b;
        }
        s += v; mx = max(mx, fenc(v)); c++;
    }
    if (c > 0) {
        atomicAdd(&g_rsum[curb * HID + j], s);
        atomicMax(&g_rmax[curb * HID + j], mx);
        if (j == 0) atomicAdd(&g_rcnt[curb], c);
    }
}
__global__ void readout_final_kernel(const float* __restrict__ roW,
                                     const float* __restrict__ roB,
                                     float* __restrict__ out) {
    __shared__ float s[2 * HID];
    int g = blockIdx.x, j = threadIdx.x;
    int cnt = g_rcnt[g];
    float mv = g_rsum[g * HID + j] / fmaxf((float)cnt, 1.f);
    float xv = (cnt > 0) ? fdec(g_rmax[g * HID + j]) : 0.f;
    s[j] = mv;
    s[HID + j] = xv;
    __syncthreads();
    float acc = roB[j];
    for (int k = 0; k < 2 * HID; k++) acc += s[k] * roW[k * HID + j];
    out[g * HID + j] = fmaxf(acc, 0.f);
}

// ---------------- launch ----------------
extern "C" void kernel_launch(void* const* d_in, const int* in_sizes, int n_in,
                              void* d_out, int out_size) {
    int base = (in_sizes[4] <= 2) ? 5 : 4;
    const float* x     = (const float*)d_in[0];
    const int*   eidx  = (const int*)d_in[1];
    const float* eattr = (const float*)d_in[2];
    const int*   batch = (const int*)d_in[3];
    const float* linW  = (const float*)d_in[base + 0];
    const float* linB  = (const float*)d_in[base + 1];
    const float* w1    = (const float*)d_in[base + 2];
    const float* b1    = (const float*)d_in[base + 3];
    const float* w2    = (const float*)d_in[base + 4];
    const float* b2    = (const float*)d_in[base + 5];
    const float* bng   = (const float*)d_in[base + 6];
    const float* bnb   = (const float*)d_in[base + 7];
    const float* bnm   = (const float*)d_in[base + 8];
    const float* bnv   = (const float*)d_in[base + 9];
    const float* wih   = (const float*)d_in[base + 10];
    const float* whh   = (const float*)d_in[base + 11];
    const float* bih   = (const float*)d_in[base + 12];
    const float* bhh   = (const float*)d_in[base + 13];
    const float* roW   = (const float*)d_in[base + 14];
    const float* roB   = (const float*)d_in[base + 15];
    float* out = (float*)d_out;

    cudaFuncSetAttribute(pdense,      cudaFuncAttributeMaxDynamicSharedMemorySize, PD_SMEM);
    cudaFuncSetAttribute(edge_kernel, cudaFuncAttributeMaxDynamicSharedMemorySize, EDGE_SMEM);

    float *hp, *aggp, *pp, *gip, *ghp, *bfp;
    unsigned *wpk, *wfpk;
    cudaGetSymbolAddress((void**)&hp,   g_h);
    cudaGetSymbolAddress((void**)&aggp, g_agg);
    cudaGetSymbolAddress((void**)&pp,   g_p);
    cudaGetSymbolAddress((void**)&gip,  g_gi);
    cudaGetSymbolAddress((void**)&ghp,  g_gh);
    cudaGetSymbolAddress((void**)&wpk,  g_wpack);
    cudaGetSymbolAddress((void**)&wfpk, g_wfpk);
    cudaGetSymbolAddress((void**)&bfp,  g_bf);

    // one-time setup: packs, fused weights, degree histogram
    pack_all<<<(25 * 16384 + 3 * 2048 + 511) / 512, 512>>>(linW, w1, wih, whh, w2);
    wfuse_kernel<<<(9 * 16384 + 3 * 384 + 255) / 256, 256>>>(w2, wih, b2);
    deg_zero<<<(N_NODES + 255) / 256, 256>>>();
    deg_build<<<(N_EDGES + 255) / 256, 256>>>(eidx + N_EDGES);

    // h = relu(x @ linW + linB)
    pdense<<<dim3(148, 1), 512, PD_SMEM>>>(x, wpk, linB, hp,
                                           x, wpk, linB, hp,
                                           N_NODES, 128, 1, 1);
    zero_agg_kernel<<<(N_NODES * HID / 4 + 255) / 256, 256>>>();

    for (int l = 0; l < N_LAYERS; l++) {
        // P = h @ W1h + b1
        pdense<<<dim3(148, 1), 512, PD_SMEM>>>(
            hp, wpk + (size_t)(1 + l) * SLAB_WORDS, b1 + l * 128, pp,
            hp, wpk + (size_t)(1 + l) * SLAB_WORDS, b1 + l * 128, pp,
            N_NODES, 128, 1, 0);
        // edge: scatter relu(P[src] + e@W1e) into g_agg  (2 CTAs/SM)
        edge_kernel<<<296, 256, EDGE_SMEM>>>(
            eattr, eidx, eidx + N_EDGES,
            wpk + (size_t)25 * SLAB_WORDS + (size_t)l * W1E_WORDS);
        // gi = H_agg @ Wfused + bih   |   gh = h @ whhT + bhh
        pdense<<<dim3(24, 6), 512, PD_SMEM>>>(
            aggp, wfpk + (size_t)(3 * l) * SLAB_WORDS, bih + l * 384, gip,
            hp,   wpk + (size_t)(13 + 3 * l) * SLAB_WORDS, bhh + l * 384, ghp,
            N_NODES, 384, 3, 0);
        gru_epi_kernel<<<(N_NODES * HID + 255) / 256, 256>>>(
            bng + l * 128, bnb + l * 128, bnm + l * 128, bnv + l * 128,
            bfp + l * 384);
    }

    zero_readout_kernel<<<(N_GRAPHS * HID + 255) / 256, 256>>>();
    readout_acc_kernel<<<(N_NODES + 127) / 128, 128>>>(batch);
    readout_final_kernel<<<N_GRAPHS, HID>>>(roW, roB, out);
}